// round 12
// baseline (speedup 1.0000x reference)
#include <cuda_runtime.h>
#include <cuda_bf16.h>
#include <math_constants.h>

// ---------------------------------------------------------------------------
// GAT (2 layers, heads=1) on GB300.
// Inputs (metadata order):
//  0: x          [N,64] f32
//  1: edge_index [2,E]  int32 OR int64 (JAX x64-disabled downgrades int64->int32;
//                                       detected at runtime on device)
//  2: W1_src [64,64]  3: W1_dst [64,64]  4: att1_src[64]  5: att1_dst[64]
//  6: b1[64]  7: Wl1[64,64]  8: bl1[64]
//  9: W2_src  10: W2_dst  11: att2_src  12: att2_dst  13: b2  14: Wl2  15: bl2
// Output: [N,64] f32
// ---------------------------------------------------------------------------

#define NMAX 50000
#define EMAX 1200000
#define C    64
#define SH_E 256   // max in-degree handled by the fast shared-memory path

// -------------------- scratch (device globals; no allocs) ------------------
__device__ float g_hsrc[NMAX * C];   // x @ W_src (per layer, reused)
__device__ float g_lin [NMAX * C];   // x @ W_lin (residual, per layer, reused)
__device__ float g_h   [NMAX * C];   // layer-1 output == layer-2 input
__device__ float g_asrc[NMAX];
__device__ float g_adst[NMAX];
__device__ float g_v   [C];          // W_dst @ att_dst (folded vector)
__device__ int   g_deg   [NMAX];
__device__ int   g_rowptr[NMAX + 1];
__device__ int   g_cursor[NMAX];
__device__ int   g_esrc  [EMAX];     // src ids sorted by dst (CSR)
__device__ int   g_bsums [64];
__device__ int   g_is64;             // edge_index dtype flag (computed per run)

// ------------------------ dtype detection -----------------------------------
// Genuine int64 indices are all < N; int32 data misread as int64 combines two
// random indices -> almost surely >= N. Recomputed every launch (deterministic).
__global__ void detect_kernel(const long long* __restrict__ ei, int N) {
    if (threadIdx.x == 0 && blockIdx.x == 0) {
        int is64 = 1;
        for (int i = 0; i < 64; i++) {
            long long v = ei[i];
            if (v < 0 || v >= N) { is64 = 0; break; }
        }
        g_is64 = is64;
    }
}

__device__ __forceinline__ int load_edge(const void* ei, long long idx, int is64) {
    if (is64) return (int)((const long long*)ei)[idx];
    return ((const int*)ei)[idx];
}

// -------------------------- CSR construction -------------------------------
__global__ void zero_deg_kernel(int N) {
    int i = blockIdx.x * blockDim.x + threadIdx.x;
    if (i < N) g_deg[i] = 0;
}

__global__ void hist_kernel(const void* __restrict__ ei, int E, int N) {
    int e = blockIdx.x * blockDim.x + threadIdx.x;
    if (e < E) {
        int d = load_edge(ei, (long long)E + e, g_is64);
        if ((unsigned)d < (unsigned)N) atomicAdd(&g_deg[d], 1);
    }
}

// per-block exclusive scan (1024 elems/block), block totals -> g_bsums
__global__ void scan_block_kernel(int N) {
    __shared__ int sh[1024];
    int i = blockIdx.x * 1024 + threadIdx.x;
    int v = (i < N) ? g_deg[i] : 0;
    sh[threadIdx.x] = v;
    __syncthreads();
    for (int o = 1; o < 1024; o <<= 1) {
        int t = 0;
        if ((int)threadIdx.x >= o) t = sh[threadIdx.x - o];
        __syncthreads();
        sh[threadIdx.x] += t;
        __syncthreads();
    }
    int incl = sh[threadIdx.x];
    if (i < N) g_rowptr[i] = incl - v;            // exclusive within block
    if (threadIdx.x == 1023) g_bsums[blockIdx.x] = incl;
}

__global__ void scan_bsums_kernel(int nb) {
    if (threadIdx.x == 0 && blockIdx.x == 0) {
        int acc = 0;
        for (int b = 0; b < nb; b++) { int t = g_bsums[b]; g_bsums[b] = acc; acc += t; }
    }
}

__global__ void add_off_kernel(int N, int E) {
    int i = blockIdx.x * blockDim.x + threadIdx.x;
    if (i < N) {
        int v = g_rowptr[i] + g_bsums[i >> 10];
        g_rowptr[i] = v;
        g_cursor[i] = v;
    }
    if (i == 0) g_rowptr[N] = E;
}

__global__ void scatter_kernel(const void* __restrict__ ei, int E, int N) {
    int e = blockIdx.x * blockDim.x + threadIdx.x;
    if (e < E) {
        int is64 = g_is64;
        int d = load_edge(ei, (long long)E + e, is64);
        int s = load_edge(ei, e, is64);
        if ((unsigned)d < (unsigned)N && (unsigned)s < (unsigned)N) {
            int pos = atomicAdd(&g_cursor[d], 1);
            if ((unsigned)pos < (unsigned)E) g_esrc[pos] = s;
        }
    }
}

// ------------------------- per-layer node kernels ---------------------------
// v[k] = sum_j W_dst[k][j] * att_dst[j]
__global__ void prep_v_kernel(const float* __restrict__ Wdst,
                              const float* __restrict__ attd) {
    int k = threadIdx.x;
    if (k < C) {
        float a = 0.f;
#pragma unroll
        for (int j = 0; j < C; j++) a += Wdst[k * C + j] * attd[j];
        g_v[k] = a;
    }
}

// Per node: h_src row, lin row, a_src scalar, a_dst scalar.
__global__ __launch_bounds__(256)
void proj_kernel(const float* __restrict__ xin_param,
                 const float* __restrict__ Wsrc,
                 const float* __restrict__ Wlin,
                 const float* __restrict__ att_src,
                 int from_gh, int N) {
    __shared__ float sWs[C * C];
    __shared__ float sWl[C * C];
    __shared__ float sAtt[C];
    __shared__ float sV[C];
    for (int i = threadIdx.x; i < C * C; i += 256) { sWs[i] = Wsrc[i]; sWl[i] = Wlin[i]; }
    if (threadIdx.x < C) { sAtt[threadIdx.x] = att_src[threadIdx.x]; sV[threadIdx.x] = g_v[threadIdx.x]; }
    __syncthreads();

    int n = blockIdx.x * 256 + threadIdx.x;
    if (n >= N) return;

    const float* xin = from_gh ? g_h : xin_param;
    float xr[C];
    const float4* xp = (const float4*)(xin + (size_t)n * C);
#pragma unroll
    for (int k = 0; k < C / 4; k++) {
        float4 t = xp[k];
        xr[4 * k] = t.x; xr[4 * k + 1] = t.y; xr[4 * k + 2] = t.z; xr[4 * k + 3] = t.w;
    }

    float ad = 0.f;
#pragma unroll
    for (int k = 0; k < C; k++) ad += xr[k] * sV[k];
    g_adst[n] = ad;

    float as = 0.f;
    // h_src = xr @ Wsrc, a_src = h_src . att_src
    for (int jc = 0; jc < C; jc += 16) {
        float acc[16];
#pragma unroll
        for (int j = 0; j < 16; j++) acc[j] = 0.f;
#pragma unroll
        for (int k = 0; k < C; k++) {
            float xv = xr[k];
            const float4* wr = (const float4*)(sWs + k * C + jc);
#pragma unroll
            for (int j4 = 0; j4 < 4; j4++) {
                float4 w = wr[j4];
                acc[4 * j4]     += xv * w.x;
                acc[4 * j4 + 1] += xv * w.y;
                acc[4 * j4 + 2] += xv * w.z;
                acc[4 * j4 + 3] += xv * w.w;
            }
        }
        float4* hp = (float4*)(g_hsrc + (size_t)n * C + jc);
#pragma unroll
        for (int j4 = 0; j4 < 4; j4++)
            hp[j4] = make_float4(acc[4 * j4], acc[4 * j4 + 1], acc[4 * j4 + 2], acc[4 * j4 + 3]);
#pragma unroll
        for (int j = 0; j < 16; j++) as += acc[j] * sAtt[jc + j];
    }
    g_asrc[n] = as;

    // lin = xr @ Wlin
    for (int jc = 0; jc < C; jc += 16) {
        float acc[16];
#pragma unroll
        for (int j = 0; j < 16; j++) acc[j] = 0.f;
#pragma unroll
        for (int k = 0; k < C; k++) {
            float xv = xr[k];
            const float4* wr = (const float4*)(sWl + k * C + jc);
#pragma unroll
            for (int j4 = 0; j4 < 4; j4++) {
                float4 w = wr[j4];
                acc[4 * j4]     += xv * w.x;
                acc[4 * j4 + 1] += xv * w.y;
                acc[4 * j4 + 2] += xv * w.z;
                acc[4 * j4 + 3] += xv * w.w;
            }
        }
        float4* lp = (float4*)(g_lin + (size_t)n * C + jc);
#pragma unroll
        for (int j4 = 0; j4 < 4; j4++)
            lp[j4] = make_float4(acc[4 * j4], acc[4 * j4 + 1], acc[4 * j4 + 2], acc[4 * j4 + 3]);
    }
}

// ------------------------- edge aggregation ---------------------------------
// One warp per dst node. Pass 1 (lane-parallel): scores -> shared, warp max.
// Pass 1b: exp weights -> shared, warp sum. Pass 2 (serial over edges, lanes
// own 2 columns each): acc += w * h_src[s]. Epilogue fuses softmax divide +
// bias + residual + ReLU.
__global__ __launch_bounds__(256)
void edge_kernel(const float* __restrict__ bias,
                 const float* __restrict__ blin,
                 float* __restrict__ out_param,
                 int to_gh, int N) {
    __shared__ int   sh_s[8][SH_E];
    __shared__ float sh_w[8][SH_E];
    int wid  = threadIdx.x >> 5;
    int lane = threadIdx.x & 31;
    int n = blockIdx.x * 8 + wid;
    if (n >= N) return;

    int start = g_rowptr[n], end = g_rowptr[n + 1];
    int deg = end - start;

    float2 acc = make_float2(0.f, 0.f);
    float invs = 0.f;

    if (deg > 0) {
        float adn = g_adst[n];
        float m = -CUDART_INF_F;
        const float2* hp = (const float2*)g_hsrc;

        if (deg <= SH_E) {
            for (int i = lane; i < deg; i += 32) {
                int s = g_esrc[start + i];
                float ev = g_asrc[s] + adn;
                ev = (ev >= 0.f) ? ev : 0.2f * ev;
                sh_s[wid][i] = s;
                sh_w[wid][i] = ev;
                m = fmaxf(m, ev);
            }
#pragma unroll
            for (int o = 16; o > 0; o >>= 1) m = fmaxf(m, __shfl_xor_sync(0xffffffff, m, o));

            float sum = 0.f;
            for (int i = lane; i < deg; i += 32) {
                float w = __expf(sh_w[wid][i] - m);
                sh_w[wid][i] = w;
                sum += w;
            }
#pragma unroll
            for (int o = 16; o > 0; o >>= 1) sum += __shfl_xor_sync(0xffffffff, sum, o);
            __syncwarp();

#pragma unroll 4
            for (int i = 0; i < deg; i++) {
                int s   = sh_s[wid][i];
                float w = sh_w[wid][i];
                float2 hv = hp[(size_t)s * 32 + lane];
                acc.x += w * hv.x;
                acc.y += w * hv.y;
            }
            invs = 1.f / sum;
        } else {
            // fallback (degree > SH_E; statistically never hit at E/N = 24)
            for (int i = lane; i < deg; i += 32) {
                int s = g_esrc[start + i];
                float ev = g_asrc[s] + adn;
                ev = (ev >= 0.f) ? ev : 0.2f * ev;
                m = fmaxf(m, ev);
            }
#pragma unroll
            for (int o = 16; o > 0; o >>= 1) m = fmaxf(m, __shfl_xor_sync(0xffffffff, m, o));
            float sum = 0.f;
            for (int i = 0; i < deg; i++) {
                int s = g_esrc[start + i];
                float ev = g_asrc[s] + adn;
                ev = (ev >= 0.f) ? ev : 0.2f * ev;
                float w = __expf(ev - m);
                sum += w;
                float2 hv = hp[(size_t)s * 32 + lane];
                acc.x += w * hv.x;
                acc.y += w * hv.y;
            }
            invs = 1.f / sum;
        }
    }

    int c0 = 2 * lane;
    float2 lv = ((const float2*)(g_lin + (size_t)n * C))[lane];
    float v0 = acc.x * invs + bias[c0]     + lv.x + blin[c0];
    float v1 = acc.y * invs + bias[c0 + 1] + lv.y + blin[c0 + 1];
    v0 = fmaxf(v0, 0.f);
    v1 = fmaxf(v1, 0.f);
    float* op = to_gh ? g_h : out_param;
    ((float2*)(op + (size_t)n * C))[lane] = make_float2(v0, v1);
}

// ------------------------------- launch -------------------------------------
extern "C" void kernel_launch(void* const* d_in, const int* in_sizes, int n_in,
                              void* d_out, int out_size) {
    const float*     x      = (const float*)d_in[0];
    const void*      ei     = d_in[1];
    const float*     W1s    = (const float*)d_in[2];
    const float*     W1d    = (const float*)d_in[3];
    const float*     att1s  = (const float*)d_in[4];
    const float*     att1d  = (const float*)d_in[5];
    const float*     b1     = (const float*)d_in[6];
    const float*     Wl1    = (const float*)d_in[7];
    const float*     bl1    = (const float*)d_in[8];
    const float*     W2s    = (const float*)d_in[9];
    const float*     W2d    = (const float*)d_in[10];
    const float*     att2s  = (const float*)d_in[11];
    const float*     att2d  = (const float*)d_in[12];
    const float*     b2     = (const float*)d_in[13];
    const float*     Wl2    = (const float*)d_in[14];
    const float*     bl2    = (const float*)d_in[15];
    float*           out    = (float*)d_out;

    int N = in_sizes[0] / C;         // 50000
    int E = in_sizes[1] / 2;         // 1200000

    int nbN  = (N + 255) / 256;
    int nbE  = (E + 255) / 256;
    int nbSc = (N + 1023) / 1024;
    int nbW  = (N + 7) / 8;

    // ---- edge dtype detection + CSR build (shared by both layers) ----
    detect_kernel<<<1, 32>>>((const long long*)ei, N);
    zero_deg_kernel<<<nbN, 256>>>(N);
    hist_kernel<<<nbE, 256>>>(ei, E, N);
    scan_block_kernel<<<nbSc, 1024>>>(N);
    scan_bsums_kernel<<<1, 32>>>(nbSc);
    add_off_kernel<<<nbN, 256>>>(N, E);
    scatter_kernel<<<nbE, 256>>>(ei, E, N);

    // ---- layer 1: x -> g_h ----
    prep_v_kernel<<<1, 64>>>(W1d, att1d);
    proj_kernel<<<nbN, 256>>>(x, W1s, Wl1, att1s, /*from_gh=*/0, N);
    edge_kernel<<<nbW, 256>>>(b1, bl1, out, /*to_gh=*/1, N);

    // ---- layer 2: g_h -> out ----
    prep_v_kernel<<<1, 64>>>(W2d, att2d);
    proj_kernel<<<nbN, 256>>>(x /*ignored*/, W2s, Wl2, att2s, /*from_gh=*/1, N);
    edge_kernel<<<nbW, 256>>>(b2, bl2, out, /*to_gh=*/0, N);
}